// round 3
// baseline (speedup 1.0000x reference)
#include <cuda_runtime.h>

#define NN    4096   // nodes
#define ED    1024   // embedding dim
#define WF    1024   // wFeat
#define NEGI  (-1e9f)

// ---------------- scratch (device globals; no allocation allowed) ----------------
__device__ float g_words[NN * ED];     // 16 MB
__device__ float g_h[NN * WF];         // 16 MB
__device__ float g_s[2 * NN];          // s_src | s_dst
__device__ float g_poolpart[16 * WF];

// ---------------- embedding gather ----------------
// inSen may arrive as int32 (JAX x64 disabled) or int64. Tokens < 2^31, so if
// the buffer is int64(LE) every odd 32-bit word is 0. Detect on 4 samples.
__global__ void embed_kernel(const int* __restrict__ sen,
                             const float* __restrict__ emb) {
    const long long* sen64 = (const long long*)sen;
    bool is64 = (sen[1] == 0 && sen[3] == 0 && sen[5] == 0 && sen[7] == 0);
    int i = blockIdx.x;
    long long tok = is64 ? sen64[i] : (long long)sen[i];
    const float4* src = (const float4*)(emb + (size_t)tok * ED);
    float4* dst = (float4*)(g_words + (size_t)i * ED);
    for (int d = threadIdx.x; d < ED / 4; d += blockDim.x) dst[d] = src[d];
}

// ---------------- fp32 SGEMM: C[M,N] = A[M,K] @ B[K,N], all row-major ----------------
// BM=BN=128, BK=16, 8x8 microtile, 256 threads. M%128==0, N%128==0, K%16==0.
#define BM 128
#define BN 128
#define BK 16
#define TM 8
#define TN 8

__global__ void __launch_bounds__(256)
sgemm_kernel(const float* __restrict__ A, const float* __restrict__ B,
             float* __restrict__ C, int M, int N, int K) {
    __shared__ __align__(16) float As[BK][BM];   // transposed A tile
    __shared__ __align__(16) float Bs[BK][BN];

    const int bx = blockIdx.x;            // N tile
    const int by = blockIdx.y;            // M tile
    const int tid = threadIdx.x;
    const int tx = tid % (BN / TN);       // 0..15
    const int ty = tid / (BN / TN);       // 0..15

    const int aRow = tid >> 2;            // 0..63
    const int aCol = (tid & 3) << 2;      // 0,4,8,12
    const int bRow = tid >> 5;            // 0..7
    const int bCol = (tid & 31) << 2;     // 0..124

    const float* Ab = A + (size_t)by * BM * K;
    const float* Bb = B + (size_t)bx * BN;

    float acc[TM][TN];
    #pragma unroll
    for (int m = 0; m < TM; m++)
        #pragma unroll
        for (int n = 0; n < TN; n++) acc[m][n] = 0.f;

    for (int k0 = 0; k0 < K; k0 += BK) {
        // A tile -> As (transposed): 128x16 floats, 2 float4 per thread
        #pragma unroll
        for (int i = 0; i < BM; i += 64) {
            float4 v = *(const float4*)(Ab + (size_t)(aRow + i) * K + k0 + aCol);
            As[aCol + 0][aRow + i] = v.x;
            As[aCol + 1][aRow + i] = v.y;
            As[aCol + 2][aRow + i] = v.z;
            As[aCol + 3][aRow + i] = v.w;
        }
        // B tile -> Bs: 16x128 floats, 2 float4 per thread
        #pragma unroll
        for (int i = 0; i < BK; i += 8) {
            *(float4*)(&Bs[bRow + i][bCol]) =
                *(const float4*)(Bb + (size_t)(k0 + bRow + i) * N + bCol);
        }
        __syncthreads();

        #pragma unroll
        for (int kk = 0; kk < BK; kk++) {
            float4 a0 = *(const float4*)(&As[kk][ty * TM]);
            float4 a1 = *(const float4*)(&As[kk][ty * TM + 4]);
            float4 b0 = *(const float4*)(&Bs[kk][tx * TN]);
            float4 b1 = *(const float4*)(&Bs[kk][tx * TN + 4]);
            float ar[TM] = {a0.x, a0.y, a0.z, a0.w, a1.x, a1.y, a1.z, a1.w};
            float br[TN] = {b0.x, b0.y, b0.z, b0.w, b1.x, b1.y, b1.z, b1.w};
            #pragma unroll
            for (int m = 0; m < TM; m++)
                #pragma unroll
                for (int n = 0; n < TN; n++)
                    acc[m][n] += ar[m] * br[n];
        }
        __syncthreads();
    }

    #pragma unroll
    for (int m = 0; m < TM; m++) {
        float* Crow = C + (size_t)(by * BM + ty * TM + m) * N + bx * BN + tx * TN;
        #pragma unroll
        for (int n = 0; n < TN; n += 4) {
            float4 v = {acc[m][n], acc[m][n + 1], acc[m][n + 2], acc[m][n + 3]};
            *(float4*)(Crow + n) = v;
        }
    }
}

// ---------------- s_src/s_dst: per-row dual dot products ----------------
__global__ void row_dots_kernel(const float* __restrict__ a_src,
                                const float* __restrict__ a_dst) {
    int i = blockIdx.x;
    const float4* hr  = (const float4*)(g_h + (size_t)i * WF);
    const float4* as4 = (const float4*)a_src;
    const float4* ad4 = (const float4*)a_dst;
    float s0 = 0.f, s1 = 0.f;
    for (int d = threadIdx.x; d < WF / 4; d += blockDim.x) {
        float4 v = hr[d], a = as4[d], b = ad4[d];
        s0 += v.x * a.x + v.y * a.y + v.z * a.z + v.w * a.w;
        s1 += v.x * b.x + v.y * b.y + v.z * b.z + v.w * b.w;
    }
    __shared__ float r0[8], r1[8];
    #pragma unroll
    for (int off = 16; off > 0; off >>= 1) {
        s0 += __shfl_down_sync(0xFFFFFFFFu, s0, off);
        s1 += __shfl_down_sync(0xFFFFFFFFu, s1, off);
    }
    int warp = threadIdx.x >> 5, lane = threadIdx.x & 31;
    if (lane == 0) { r0[warp] = s0; r1[warp] = s1; }
    __syncthreads();
    if (threadIdx.x == 0) {
        float t0 = 0.f, t1 = 0.f;
        for (int w = 0; w < 8; w++) { t0 += r0[w]; t1 += r1[w]; }
        g_s[i] = t0;
        g_s[NN + i] = t1;
    }
}

// ---------------- masked softmax row kernel (single pass over adj) ----------------
__global__ void attn_kernel(const int* __restrict__ adj,
                            float* __restrict__ att) {
    __shared__ float ebuf[NN];        // 16 KB: full row of e
    __shared__ float red[8];
    const int i = blockIdx.x;
    const int tid = threadIdx.x;
    const int warp = tid >> 5, lane = tid & 31;
    const float si = g_s[i];
    const int* arow = adj + (size_t)i * NN;
    const float* sdst = g_s + NN;

    float mx = -3.0e38f;
    for (int j = tid; j < NN; j += 256) {
        float e;
        if (arow[j] > 0) {
            float x = si + sdst[j];
            e = x > 0.f ? x : 0.01f * x;
        } else {
            e = NEGI;
        }
        ebuf[j] = e;
        mx = fmaxf(mx, e);
    }
    #pragma unroll
    for (int off = 16; off > 0; off >>= 1)
        mx = fmaxf(mx, __shfl_down_sync(0xFFFFFFFFu, mx, off));
    if (lane == 0) red[warp] = mx;
    __syncthreads();
    if (warp == 0) {
        float v = (lane < 8) ? red[lane] : -3.0e38f;
        #pragma unroll
        for (int off = 4; off > 0; off >>= 1)
            v = fmaxf(v, __shfl_down_sync(0xFFFFFFFFu, v, off));
        if (lane == 0) red[0] = v;
    }
    __syncthreads();
    mx = red[0];
    __syncthreads();

    float sum = 0.f;
    for (int j = tid; j < NN; j += 256) {
        float p = expf(ebuf[j] - mx);
        ebuf[j] = p;
        sum += p;
    }
    #pragma unroll
    for (int off = 16; off > 0; off >>= 1)
        sum += __shfl_down_sync(0xFFFFFFFFu, sum, off);
    if (lane == 0) red[warp] = sum;
    __syncthreads();
    if (warp == 0) {
        float v = (lane < 8) ? red[lane] : 0.f;
        #pragma unroll
        for (int off = 4; off > 0; off >>= 1)
            v += __shfl_down_sync(0xFFFFFFFFu, v, off);
        if (lane == 0) red[0] = v;
    }
    __syncthreads();
    const float inv = 1.0f / red[0];
    float* orow = att + (size_t)i * NN;
    for (int j = tid; j < NN; j += 256) orow[j] = ebuf[j] * inv;
}

// ---------------- mean pool (two-stage, deterministic: no atomics) ----------------
__global__ void pool_partial_kernel(const float* __restrict__ sentence) {
    int d = blockIdx.x * 256 + threadIdx.x;       // 0..1023
    int i0 = blockIdx.y * 256;                    // 16 chunks of 256 rows
    float sum = 0.f;
    for (int i = i0; i < i0 + 256; i++)
        sum += sentence[(size_t)i * WF + d];
    g_poolpart[blockIdx.y * WF + d] = sum;
}

__global__ void pool_final_kernel(float* __restrict__ pool) {
    int d = blockIdx.x * 256 + threadIdx.x;
    float sum = 0.f;
    #pragma unroll
    for (int p = 0; p < 16; p++) sum += g_poolpart[p * WF + d];
    pool[d] = sum * (1.0f / (float)NN);
}

// ---------------- classifier ----------------
__global__ void classify_kernel(const float* __restrict__ pool,
                                const float* __restrict__ clf_w,
                                const float* __restrict__ clf_b,
                                float* __restrict__ label) {
    int tid = threadIdx.x;
    float s0 = 0.f, s1 = 0.f;
    for (int d = tid; d < WF; d += 256) {
        float p = pool[d];
        s0 += p * clf_w[2 * d];
        s1 += p * clf_w[2 * d + 1];
    }
    __shared__ float r0[8], r1[8];
    #pragma unroll
    for (int off = 16; off > 0; off >>= 1) {
        s0 += __shfl_down_sync(0xFFFFFFFFu, s0, off);
        s1 += __shfl_down_sync(0xFFFFFFFFu, s1, off);
    }
    int warp = tid >> 5, lane = tid & 31;
    if (lane == 0) { r0[warp] = s0; r1[warp] = s1; }
    __syncthreads();
    if (tid == 0) {
        float t0 = 0.f, t1 = 0.f;
        for (int w = 0; w < 8; w++) { t0 += r0[w]; t1 += r1[w]; }
        t0 += clf_b[0];
        t1 += clf_b[1];
        float m = fmaxf(t0, t1);
        float e0 = expf(t0 - m), e1 = expf(t1 - m);
        float inv = 1.0f / (e0 + e1);
        label[0] = e0 * inv;
        label[1] = e1 * inv;
    }
}

// ---------------- launch ----------------
extern "C" void kernel_launch(void* const* d_in, const int* in_sizes, int n_in,
                              void* d_out, int out_size) {
    const int*   inSen = (const int*)d_in[0];
    const int*   adj   = (const int*)d_in[1];
    const float* emb   = (const float*)d_in[2];
    const float* W     = (const float*)d_in[3];
    const float* a_src = (const float*)d_in[4];
    const float* a_dst = (const float*)d_in[5];
    const float* clf_w = (const float*)d_in[6];
    const float* clf_b = (const float*)d_in[7];
    (void)in_sizes; (void)n_in; (void)out_size;

    float* out       = (float*)d_out;
    float* out_pool  = out;                                   // [1024]
    float* out_att   = out + 1024;                            // [4096*4096]
    float* out_sent  = out + 1024 + (size_t)NN * NN;          // [4096*1024]
    float* out_label = out_sent + (size_t)NN * WF;            // [2]

    float *p_words = nullptr, *p_h = nullptr;
    cudaGetSymbolAddress((void**)&p_words, g_words);
    cudaGetSymbolAddress((void**)&p_h, g_h);

    // 1. embedding gather
    embed_kernel<<<NN, 256>>>(inSen, emb);

    // 2. h = words @ W    [4096,1024] x [1024,1024]
    sgemm_kernel<<<dim3(WF / BN, NN / BM), 256>>>(p_words, W, p_h, NN, WF, ED);

    // 3. s_src = h@a_src, s_dst = h@a_dst
    row_dots_kernel<<<NN, 256>>>(a_src, a_dst);

    // 4. attention = softmax(mask(leaky_relu(s_src[i]+s_dst[j])))
    attn_kernel<<<NN, 256>>>(adj, out_att);

    // 5. sentence = attention @ h   [4096,4096] x [4096,1024]
    sgemm_kernel<<<dim3(WF / BN, NN / BM), 256>>>(out_att, p_h, out_sent, NN, WF, NN);

    // 6. poolSentence = mean(sentence, axis=0)
    pool_partial_kernel<<<dim3(WF / 256, 16), 256>>>(out_sent);
    pool_final_kernel<<<WF / 256, 256>>>(out_pool);

    // 7. label = softmax(pool @ clf_w + clf_b)
    classify_kernel<<<1, 256>>>(out_pool, clf_w, clf_b, out_label);
}

// round 4
// speedup vs baseline: 3.0401x; 3.0401x over previous
#include <cuda_runtime.h>
#include <cstdint>

#define NN    4096   // nodes
#define ED    1024   // embedding dim
#define WF    1024   // wFeat
#define NEGI  (-1e9f)

// ---------------- scratch (device globals; no allocation allowed) ----------------
__device__ float g_h[NN * WF];         // 16 MB
__device__ float g_s[2 * NN];          // s_src | s_dst
__device__ float g_poolpart[16 * WF];
__device__ int   g_tok[NN];

// ---------------- token normalize (int32 vs int64 input) ----------------
// inSen may arrive as int32 (JAX x64 disabled) or int64. Tokens < 2^31, so if
// the buffer is little-endian int64 every odd 32-bit word is 0.
__global__ void tok_kernel(const int* __restrict__ sen) {
    int i = blockIdx.x * 256 + threadIdx.x;
    const long long* s64 = (const long long*)sen;
    bool is64 = (sen[1] == 0 && sen[3] == 0 && sen[5] == 0 && sen[7] == 0);
    if (i < NN) g_tok[i] = is64 ? (int)s64[i] : sen[i];
}

// ---------------- TF32 tensor-core GEMM ----------------
// C[M,N] = A[M,K] @ B[K,N], row-major. M%128==0, N%128==0, K%16==0.
// 128 threads = 4 warps, warp tile 64x64 via m16n8k8 tf32 mma.sync.
// Optional row gather on A (for fused embedding lookup).
#define BM 128
#define BN 128
#define BKT 16
#define AS_STRIDE 20     // 16 + 4 pad  -> conflict-free A fragment loads
#define BS_STRIDE 136    // 128 + 8 pad -> conflict-free B fragment loads

__device__ __forceinline__ float f2tf32(float x) {
    uint32_t u;
    asm("cvt.rna.tf32.f32 %0, %1;" : "=r"(u) : "f"(x));
    return __uint_as_float(u);
}

__global__ void __launch_bounds__(128)
mma_gemm(const float* __restrict__ A, const float* __restrict__ B,
         float* __restrict__ C, int M, int N, int K,
         const int* __restrict__ rowidx) {
    __shared__ __align__(16) float As[2][BM * AS_STRIDE];
    __shared__ __align__(16) float Bs[2][BKT * BS_STRIDE];

    const int tid  = threadIdx.x;
    const int lane = tid & 31;
    const int warp = tid >> 5;             // 0..3
    const int wm = (warp >> 1) * 64;       // warp row offset in tile
    const int wn = (warp & 1) * 64;       // warp col offset in tile
    const int bx = blockIdx.x, by = blockIdx.y;

    // staging thread maps
    const int ar = tid >> 2;               // 0..31 (A rows, step 32)
    const int ac = (tid & 3) << 2;         // 0,4,8,12
    const int br = tid >> 5;               // 0..3  (B rows, step 4)
    const int bc = (tid & 31) << 2;        // 0..124

    // resolve A row pointers (optional gather for embedding fusion)
    const float* Arow[4];
    #pragma unroll
    for (int i = 0; i < 4; i++) {
        int r = by * BM + ar + i * 32;
        int rr = rowidx ? rowidx[r] : r;
        Arow[i] = A + (size_t)rr * K + ac;
    }
    const float* Bp = B + (size_t)bx * BN + bc;

    float acc[4][8][4];
    #pragma unroll
    for (int mt = 0; mt < 4; mt++)
        #pragma unroll
        for (int nt = 0; nt < 8; nt++)
            #pragma unroll
            for (int q = 0; q < 4; q++) acc[mt][nt][q] = 0.f;

    float4 stA[4], stB[4];

    const int nk = K / BKT;

    // prologue: load + store tile 0
    #pragma unroll
    for (int i = 0; i < 4; i++) stA[i] = *(const float4*)(Arow[i]);
    #pragma unroll
    for (int i = 0; i < 4; i++) stB[i] = *(const float4*)(Bp + (size_t)(br + i * 4) * N);
    #pragma unroll
    for (int i = 0; i < 4; i++) {
        float4 v = stA[i];
        *(float4*)&As[0][(ar + i * 32) * AS_STRIDE + ac] =
            make_float4(f2tf32(v.x), f2tf32(v.y), f2tf32(v.z), f2tf32(v.w));
    }
    #pragma unroll
    for (int i = 0; i < 4; i++) {
        float4 v = stB[i];
        *(float4*)&Bs[0][(br + i * 4) * BS_STRIDE + bc] =
            make_float4(f2tf32(v.x), f2tf32(v.y), f2tf32(v.z), f2tf32(v.w));
    }
    __syncthreads();

    for (int kt = 0; kt < nk; kt++) {
        const int buf = kt & 1;
        const int k0g = (kt + 1) * BKT;
        if (kt + 1 < nk) {
            #pragma unroll
            for (int i = 0; i < 4; i++) stA[i] = *(const float4*)(Arow[i] + k0g);
            #pragma unroll
            for (int i = 0; i < 4; i++)
                stB[i] = *(const float4*)(Bp + (size_t)(k0g + br + i * 4) * N);
        }

        const float* Ab = As[buf];
        const float* Bb = Bs[buf];
        #pragma unroll
        for (int ks = 0; ks < 2; ks++) {
            const int k0 = ks * 8;
            uint32_t af[4][4], bf[8][2];
            #pragma unroll
            for (int mt = 0; mt < 4; mt++) {
                int r = wm + mt * 16 + (lane >> 2);
                int c = k0 + (lane & 3);
                af[mt][0] = __float_as_uint(Ab[ r      * AS_STRIDE + c]);
                af[mt][1] = __float_as_uint(Ab[(r + 8) * AS_STRIDE + c]);
                af[mt][2] = __float_as_uint(Ab[ r      * AS_STRIDE + c + 4]);
                af[mt][3] = __float_as_uint(Ab[(r + 8) * AS_STRIDE + c + 4]);
            }
            #pragma unroll
            for (int nt = 0; nt < 8; nt++) {
                int c = wn + nt * 8 + (lane >> 2);
                int r = k0 + (lane & 3);
                bf[nt][0] = __float_as_uint(Bb[ r      * BS_STRIDE + c]);
                bf[nt][1] = __float_as_uint(Bb[(r + 4) * BS_STRIDE + c]);
            }
            #pragma unroll
            for (int mt = 0; mt < 4; mt++)
                #pragma unroll
                for (int nt = 0; nt < 8; nt++)
                    asm volatile(
                        "mma.sync.aligned.m16n8k8.row.col.f32.tf32.tf32.f32 "
                        "{%0,%1,%2,%3}, {%4,%5,%6,%7}, {%8,%9}, {%0,%1,%2,%3};\n"
                        : "+f"(acc[mt][nt][0]), "+f"(acc[mt][nt][1]),
                          "+f"(acc[mt][nt][2]), "+f"(acc[mt][nt][3])
                        : "r"(af[mt][0]), "r"(af[mt][1]),
                          "r"(af[mt][2]), "r"(af[mt][3]),
                          "r"(bf[nt][0]), "r"(bf[nt][1]));
        }

        if (kt + 1 < nk) {
            const int nbuf = (kt + 1) & 1;
            #pragma unroll
            for (int i = 0; i < 4; i++) {
                float4 v = stA[i];
                *(float4*)&As[nbuf][(ar + i * 32) * AS_STRIDE + ac] =
                    make_float4(f2tf32(v.x), f2tf32(v.y), f2tf32(v.z), f2tf32(v.w));
            }
            #pragma unroll
            for (int i = 0; i < 4; i++) {
                float4 v = stB[i];
                *(float4*)&Bs[nbuf][(br + i * 4) * BS_STRIDE + bc] =
                    make_float4(f2tf32(v.x), f2tf32(v.y), f2tf32(v.z), f2tf32(v.w));
            }
        }
        __syncthreads();
    }

    // epilogue
    #pragma unroll
    for (int mt = 0; mt < 4; mt++) {
        int r0 = by * BM + wm + mt * 16 + (lane >> 2);
        #pragma unroll
        for (int nt = 0; nt < 8; nt++) {
            int c = bx * BN + wn + nt * 8 + ((lane & 3) << 1);
            *(float2*)&C[(size_t)r0 * N + c] =
                make_float2(acc[mt][nt][0], acc[mt][nt][1]);
            *(float2*)&C[(size_t)(r0 + 8) * N + c] =
                make_float2(acc[mt][nt][2], acc[mt][nt][3]);
        }
    }
}

// ---------------- s_src/s_dst: per-row dual dot products ----------------
__global__ void row_dots_kernel(const float* __restrict__ a_src,
                                const float* __restrict__ a_dst) {
    int i = blockIdx.x;
    const float4* hr  = (const float4*)(g_h + (size_t)i * WF);
    const float4* as4 = (const float4*)a_src;
    const float4* ad4 = (const float4*)a_dst;
    float s0 = 0.f, s1 = 0.f;
    for (int d = threadIdx.x; d < WF / 4; d += blockDim.x) {
        float4 v = hr[d], a = as4[d], b = ad4[d];
        s0 += v.x * a.x + v.y * a.y + v.z * a.z + v.w * a.w;
        s1 += v.x * b.x + v.y * b.y + v.z * b.z + v.w * b.w;
    }
    __shared__ float r0[8], r1[8];
    #pragma unroll
    for (int off = 16; off > 0; off >>= 1) {
        s0 += __shfl_down_sync(0xFFFFFFFFu, s0, off);
        s1 += __shfl_down_sync(0xFFFFFFFFu, s1, off);
    }
    int warp = threadIdx.x >> 5, lane = threadIdx.x & 31;
    if (lane == 0) { r0[warp] = s0; r1[warp] = s1; }
    __syncthreads();
    if (threadIdx.x == 0) {
        float t0 = 0.f, t1 = 0.f;
        for (int w = 0; w < 8; w++) { t0 += r0[w]; t1 += r1[w]; }
        g_s[i] = t0;
        g_s[NN + i] = t1;
    }
}

// ---------------- masked softmax row kernel (vectorized, single adj pass) ----------------
__global__ void attn_kernel(const int* __restrict__ adj,
                            float* __restrict__ att) {
    __shared__ __align__(16) float ebuf[NN];   // 16 KB row of e
    __shared__ float red[8];
    const int i = blockIdx.x;
    const int tid = threadIdx.x;
    const int warp = tid >> 5, lane = tid & 31;
    const float si = g_s[i];
    const int4* arow = (const int4*)(adj + (size_t)i * NN);
    const float4* sd4 = (const float4*)(g_s + NN);
    float4* eb4 = (float4*)ebuf;

    float mx = -3.0e38f;
    #pragma unroll
    for (int j = tid; j < NN / 4; j += 256) {
        int4 a = arow[j];
        float4 s = sd4[j];
        float4 e;
        float x;
        x = si + s.x; e.x = (a.x > 0) ? (x > 0.f ? x : 0.01f * x) : NEGI;
        x = si + s.y; e.y = (a.y > 0) ? (x > 0.f ? x : 0.01f * x) : NEGI;
        x = si + s.z; e.z = (a.z > 0) ? (x > 0.f ? x : 0.01f * x) : NEGI;
        x = si + s.w; e.w = (a.w > 0) ? (x > 0.f ? x : 0.01f * x) : NEGI;
        eb4[j] = e;
        mx = fmaxf(mx, fmaxf(fmaxf(e.x, e.y), fmaxf(e.z, e.w)));
    }
    #pragma unroll
    for (int off = 16; off > 0; off >>= 1)
        mx = fmaxf(mx, __shfl_down_sync(0xFFFFFFFFu, mx, off));
    if (lane == 0) red[warp] = mx;
    __syncthreads();
    if (warp == 0) {
        float v = (lane < 8) ? red[lane] : -3.0e38f;
        #pragma unroll
        for (int off = 4; off > 0; off >>= 1)
            v = fmaxf(v, __shfl_down_sync(0xFFFFFFFFu, v, off));
        if (lane == 0) red[0] = v;
    }
    __syncthreads();
    mx = red[0];
    __syncthreads();

    float sum = 0.f;
    #pragma unroll
    for (int j = tid; j < NN / 4; j += 256) {
        float4 e = eb4[j];
        e.x = __expf(e.x - mx);
        e.y = __expf(e.y - mx);
        e.z = __expf(e.z - mx);
        e.w = __expf(e.w - mx);
        eb4[j] = e;
        sum += e.x + e.y + e.z + e.w;
    }
    #pragma unroll
    for (int off = 16; off > 0; off >>= 1)
        sum += __shfl_down_sync(0xFFFFFFFFu, sum, off);
    if (lane == 0) red[warp] = sum;
    __syncthreads();
    if (warp == 0) {
        float v = (lane < 8) ? red[lane] : 0.f;
        #pragma unroll
        for (int off = 4; off > 0; off >>= 1)
            v += __shfl_down_sync(0xFFFFFFFFu, v, off);
        if (lane == 0) red[0] = v;
    }
    __syncthreads();
    const float inv = 1.0f / red[0];
    float4* orow = (float4*)(att + (size_t)i * NN);
    #pragma unroll
    for (int j = tid; j < NN / 4; j += 256) {
        float4 e = eb4[j];
        orow[j] = make_float4(e.x * inv, e.y * inv, e.z * inv, e.w * inv);
    }
}

// ---------------- mean pool (two-stage, deterministic: no atomics) ----------------
__global__ void pool_partial_kernel(const float* __restrict__ sentence) {
    int d = blockIdx.x * 256 + threadIdx.x;
    int i0 = blockIdx.y * 256;
    float sum = 0.f;
    for (int i = i0; i < i0 + 256; i++)
        sum += sentence[(size_t)i * WF + d];
    g_poolpart[blockIdx.y * WF + d] = sum;
}

__global__ void pool_final_kernel(float* __restrict__ pool) {
    int d = blockIdx.x * 256 + threadIdx.x;
    float sum = 0.f;
    #pragma unroll
    for (int p = 0; p < 16; p++) sum += g_poolpart[p * WF + d];
    pool[d] = sum * (1.0f / (float)NN);
}

// ---------------- classifier ----------------
__global__ void classify_kernel(const float* __restrict__ pool,
                                const float* __restrict__ clf_w,
                                const float* __restrict__ clf_b,
                                float* __restrict__ label) {
    int tid = threadIdx.x;
    float s0 = 0.f, s1 = 0.f;
    for (int d = tid; d < WF; d += 256) {
        float p = pool[d];
        s0 += p * clf_w[2 * d];
        s1 += p * clf_w[2 * d + 1];
    }
    __shared__ float r0[8], r1[8];
    #pragma unroll
    for (int off = 16; off > 0; off >>= 1) {
        s0 += __shfl_down_sync(0xFFFFFFFFu, s0, off);
        s1 += __shfl_down_sync(0xFFFFFFFFu, s1, off);
    }
    int warp = tid >> 5, lane = tid & 31;
    if (lane == 0) { r0[warp] = s0; r1[warp] = s1; }
    __syncthreads();
    if (tid == 0) {
        float t0 = 0.f, t1 = 0.f;
        for (int w = 0; w < 8; w++) { t0 += r0[w]; t1 += r1[w]; }
        t0 += clf_b[0];
        t1 += clf_b[1];
        float m = fmaxf(t0, t1);
        float e0 = expf(t0 - m), e1 = expf(t1 - m);
        float inv = 1.0f / (e0 + e1);
        label[0] = e0 * inv;
        label[1] = e1 * inv;
    }
}

// ---------------- launch ----------------
extern "C" void kernel_launch(void* const* d_in, const int* in_sizes, int n_in,
                              void* d_out, int out_size) {
    const int*   inSen = (const int*)d_in[0];
    const int*   adj   = (const int*)d_in[1];
    const float* emb   = (const float*)d_in[2];
    const float* W     = (const float*)d_in[3];
    const float* a_src = (const float*)d_in[4];
    const float* a_dst = (const float*)d_in[5];
    const float* clf_w = (const float*)d_in[6];
    const float* clf_b = (const float*)d_in[7];
    (void)in_sizes; (void)n_in; (void)out_size;

    float* out       = (float*)d_out;
    float* out_pool  = out;                                   // [1024]
    float* out_att   = out + 1024;                            // [4096*4096]
    float* out_sent  = out + 1024 + (size_t)NN * NN;          // [4096*1024]
    float* out_label = out_sent + (size_t)NN * WF;            // [2]

    float* p_h = nullptr;
    int*   p_tok = nullptr;
    cudaGetSymbolAddress((void**)&p_h, g_h);
    cudaGetSymbolAddress((void**)&p_tok, g_tok);

    // 1. token normalize (int64 -> int32)
    tok_kernel<<<NN / 256, 256>>>(inSen);

    // 2. h = emb[inSen] @ W  (embedding gather fused into A-load)
    mma_gemm<<<dim3(WF / BN, NN / BM), 128>>>(emb, W, p_h, NN, WF, ED, p_tok);

    // 3. s_src = h@a_src, s_dst = h@a_dst
    row_dots_kernel<<<NN, 256>>>(a_src, a_dst);

    // 4. attention = softmax(mask(leaky_relu(s_src[i]+s_dst[j])))
    attn_kernel<<<NN, 256>>>(adj, out_att);

    // 5. sentence = attention @ h
    mma_gemm<<<dim3(WF / BN, NN / BM), 128>>>(out_att, p_h, out_sent, NN, WF, NN, nullptr);

    // 6. poolSentence = mean(sentence, axis=0)
    pool_partial_kernel<<<dim3(WF / 256, 16), 256>>>(out_sent);
    pool_final_kernel<<<WF / 256, 256>>>(out_pool);

    // 7. label = softmax(pool @ clf_w + clf_b)
    classify_kernel<<<1, 256>>>(out_pool, clf_w, clf_b, out_label);
}